// round 4
// baseline (speedup 1.0000x reference)
#include <cuda_runtime.h>
#include <cstdint>

// Problem constants (fixed shapes per reference setup_inputs)
#define CIN   64
#define COUT  64
#define HH    256
#define WW    256
#define BATCH 16

// Tile config
#define TW  32   // output tile width per block
#define TH  8    // output tile height per block
#define TCO 32   // cout per block
#define CC  8    // cin chunk staged in smem
#define XP  35   // x smem row pitch (35 mod 32 = 3 -> conflict-free for (3*ty+8*tx+i))

// Scratch: quantized+duplicated weights, folded BN params
__device__ float d_Wq[CIN * 9 * COUT * 2];   // [ci][r][co][2] (dup f32x2 pairs)
__device__ float d_g[COUT];
__device__ float d_bias[COUT];

// ---------------- packed f32x2 helpers (ptxas won't emit these from C++) -----
__device__ __forceinline__ unsigned long long pack2(float lo, float hi) {
    unsigned long long r;
    asm("mov.b64 %0, {%1, %2};" : "=l"(r) : "f"(lo), "f"(hi));
    return r;
}
__device__ __forceinline__ void fma2(unsigned long long& d,
                                     unsigned long long a, unsigned long long b) {
    asm("fma.rn.f32x2 %0, %1, %2, %0;" : "+l"(d) : "l"(a), "l"(b));
}
__device__ __forceinline__ void add2(unsigned long long& d, unsigned long long a) {
    asm("add.rn.f32x2 %0, %1, %0;" : "+l"(d) : "l"(a));
}
__device__ __forceinline__ float2 unpack2(unsigned long long v) {
    float2 f;
    asm("mov.b64 {%0, %1}, %2;" : "=f"(f.x), "=f"(f.y) : "l"(v));
    return f;
}

// ---------------- prep: int4 fake-quant weights + BN fold -------------------
__global__ void prep_kernel(const float* __restrict__ W,
                            const float* __restrict__ gamma,
                            const float* __restrict__ beta,
                            const float* __restrict__ mean,
                            const float* __restrict__ var) {
    int co = blockIdx.x;               // one block per output channel
    __shared__ float red[256];
    float m = 0.f;
    for (int i = threadIdx.x; i < CIN * 9; i += blockDim.x)
        m = fmaxf(m, fabsf(W[co * CIN * 9 + i]));
    red[threadIdx.x] = m;
    __syncthreads();
    for (int s = 128; s > 0; s >>= 1) {
        if (threadIdx.x < s)
            red[threadIdx.x] = fmaxf(red[threadIdx.x], red[threadIdx.x + s]);
        __syncthreads();
    }
    float scale = fmaxf(red[0] / 7.0f, 1e-8f);

    for (int i = threadIdx.x; i < CIN * 9; i += blockDim.x) {
        int ci = i / 9, r = i - ci * 9;
        float w = W[co * CIN * 9 + i];
        float q = rintf(w / scale);                 // round-half-even = jnp.round
        q = fminf(fmaxf(q, -7.f), 7.f) * scale;
        int dst = ((ci * 9 + r) * COUT + co) * 2;   // duplicated pair
        d_Wq[dst]     = q;
        d_Wq[dst + 1] = q;
    }
    if (threadIdx.x == 0) {
        float g = gamma[co] / sqrtf(var[co] + 1e-5f);
        d_g[co]    = g;
        d_bias[co] = beta[co] - mean[co] * g;
    }
}

// ---------------- main fused conv+BN+QuantReLU ------------------------------
__global__ __launch_bounds__(256, 2)
void conv_kernel(const float* __restrict__ x,
                 const float* __restrict__ act_scale,
                 float* __restrict__ out) {
    __shared__ __align__(16) float xs[CC][TH + 2][XP];
    __shared__ __align__(16) float ws[CC][9][TCO * 2];   // dup f32x2 pairs

    const int tid = threadIdx.x;
    const int tx = tid & 3;          // w-octet: pixels tx*8 .. tx*8+7
    const int ty = (tid >> 2) & 7;   // output row within tile
    const int tz = tid >> 5;         // cout quad (== warp id)

    const int w0 = blockIdx.x * TW;
    const int h0 = blockIdx.y * TH;
    const int b  = blockIdx.z >> 1;
    const int cb = (blockIdx.z & 1) * TCO;

    const float* xb = x + (size_t)b * CIN * HH * WW;
    const float2* wsrc = (const float2*)d_Wq;

    unsigned long long macc[4][4];   // master acc: [co][pixel-pair], f32x2
    #pragma unroll
    for (int a = 0; a < 4; a++)
        #pragma unroll
        for (int j = 0; j < 4; j++) macc[a][j] = 0ull;

    for (int c0 = 0; c0 < CIN; c0 += CC) {
        // ---- stage x tile (with halo, zero-padded at borders) ----
        #pragma unroll 1
        for (int i = tid; i < CC * (TH + 2) * 34; i += 256) {
            int ci  = i / ((TH + 2) * 34);
            int rem = i - ci * ((TH + 2) * 34);
            int hl  = rem / 34;
            int wl  = rem - hl * 34;
            int gh = h0 - 1 + hl;
            int gw = w0 - 1 + wl;
            float v = 0.f;
            if ((unsigned)gh < HH && (unsigned)gw < WW)
                v = xb[(size_t)(c0 + ci) * (HH * WW) + gh * WW + gw];
            xs[ci][hl][wl] = v;
        }
        // ---- stage duplicated weights for this chunk ----
        {
            float2* wsd = (float2*)ws;
            #pragma unroll 1
            for (int i = tid; i < CC * 9 * TCO; i += 256) {
                int ci  = i / (9 * TCO);
                int rem = i - ci * 9 * TCO;
                int r   = rem >> 5;
                int co  = rem & 31;
                wsd[(ci * 9 + r) * TCO + co] =
                    wsrc[((c0 + ci) * 9 + r) * COUT + cb + co];
            }
        }
        __syncthreads();

        // per-chunk partial accumulators (shorter fp32 chains -> less
        // summation noise; quant snapping amplifies ordering noise)
        unsigned long long cacc[4][4];
        #pragma unroll
        for (int a = 0; a < 4; a++)
            #pragma unroll
            for (int j = 0; j < 4; j++) cacc[a][j] = 0ull;

        #pragma unroll 2
        for (int ci = 0; ci < CC; ci++) {
            #pragma unroll
            for (int kh = 0; kh < 3; kh++) {
                float xr[10];
                #pragma unroll
                for (int i = 0; i < 10; i++)
                    xr[i] = xs[ci][ty + kh][tx * 8 + i];
                unsigned long long p[3][4];
                #pragma unroll
                for (int j = 0; j < 4; j++) {
                    p[0][j] = pack2(xr[2 * j],     xr[2 * j + 1]);
                    p[1][j] = pack2(xr[2 * j + 1], xr[2 * j + 2]);
                    p[2][j] = pack2(xr[2 * j + 2], xr[2 * j + 3]);
                }
                #pragma unroll
                for (int kw = 0; kw < 3; kw++) {
                    const unsigned long long* wp =
                        (const unsigned long long*)&ws[ci][kh * 3 + kw][0];
                    unsigned long long wv[4];
                    #pragma unroll
                    for (int co = 0; co < 4; co++) wv[co] = wp[tz * 4 + co];
                    #pragma unroll
                    for (int co = 0; co < 4; co++)
                        #pragma unroll
                        for (int j = 0; j < 4; j++)
                            fma2(cacc[co][j], p[kw][j], wv[co]);
                }
            }
        }
        #pragma unroll
        for (int a = 0; a < 4; a++)
            #pragma unroll
            for (int j = 0; j < 4; j++) add2(macc[a][j], cacc[a][j]);
        __syncthreads();
    }

    // ---- epilogue: BN (folded) + ReLU + uint4 fake-quant ----
    const float s = fmaxf(act_scale[0], 1e-8f);
    const int h = h0 + ty;
    const int wbase = w0 + tx * 8;
    #pragma unroll
    for (int co = 0; co < 4; co++) {
        const int c = cb + tz * 4 + co;
        const float g  = d_g[c];
        const float bi = d_bias[c];
        float* op = out + (((size_t)b * COUT + c) * HH + h) * WW + wbase;
        #pragma unroll
        for (int j = 0; j < 4; j++) {
            float2 v = unpack2(macc[co][j]);
            float y0 = fmaxf(fmaf(v.x, g, bi), 0.f);
            float y1 = fmaxf(fmaf(v.y, g, bi), 0.f);
            float q0 = fminf(rintf(y0 / s), 15.f);   // IEEE div + half-even
            float q1 = fminf(rintf(y1 / s), 15.f);
            float2 o;
            o.x = q0 * s;
            o.y = q1 * s;
            *(float2*)(op + 2 * j) = o;
        }
    }
}

// ---------------- harness entry ---------------------------------------------
extern "C" void kernel_launch(void* const* d_in, const int* in_sizes, int n_in,
                              void* d_out, int out_size) {
    const float* x     = (const float*)d_in[0];
    const float* W     = (const float*)d_in[1];
    const float* gamma = (const float*)d_in[2];
    const float* beta  = (const float*)d_in[3];
    const float* mean  = (const float*)d_in[4];
    const float* var   = (const float*)d_in[5];
    const float* act   = (const float*)d_in[6];
    float* out = (float*)d_out;
    (void)in_sizes; (void)n_in; (void)out_size;

    prep_kernel<<<COUT, 256>>>(W, gamma, beta, mean, var);
    dim3 grid(WW / TW, HH / TH, BATCH * 2);
    conv_kernel<<<grid, 256>>>(x, act, out);
}

// round 7
// speedup vs baseline: 4.2706x; 4.2706x over previous
#include <cuda_runtime.h>
#include <cuda_fp16.h>
#include <cstdint>

#define HH    256
#define WW    256
#define BATCH 16
#define CIN   64
#define COUT  64
#define TH    8      // output rows per CTA

// ---- smem layout (byte offsets from dynamic smem base) ---------------------
#define XSLOT   144                    // 64 fp16 ci (128B) + 16B pad -> bank-walk
#define XROW_SPLIT (130 * XSLOT)       // 18720 bytes: one split of one row
#define ROWBUF  (2 * XROW_SPLIT)       // hi + lo = 37440
#define XS_BYTES (3 * ROWBUF)          // ring of 3 rows = 112320
#define WB_OFF   XS_BYTES
#define WTAP     (64 * XSLOT)          // 9216 per tap (co rows, padded)
#define WB_BYTES (9 * WTAP)            // 82944
#define MISC_OFF (WB_OFF + WB_BYTES)   // 195264
#define SMEM_REQ (MISC_OFF + 1024)     // 196288 (< 227KB dyn limit)

// Scratch globals
__device__ __align__(16) __half d_Wh[9 * 64 * 64];  // [tap][co][ci] fp16 int weights
__device__ float d_g[COUT];
__device__ float d_bias[COUT];

__device__ __forceinline__ uint32_t smem_u32(const void* p) {
    uint32_t a;
    asm("{ .reg .u64 t; cvta.to.shared.u64 t, %1; cvt.u32.u64 %0, t; }" : "=r"(a) : "l"(p));
    return a;
}
__device__ __forceinline__ void ldsm_x4(uint32_t* r, uint32_t addr) {
    asm volatile("ldmatrix.sync.aligned.m8n8.x4.shared.b16 {%0,%1,%2,%3}, [%4];"
                 : "=r"(r[0]), "=r"(r[1]), "=r"(r[2]), "=r"(r[3]) : "r"(addr));
}
__device__ __forceinline__ void mma16816(float* c, const uint32_t* a,
                                         uint32_t b0, uint32_t b1) {
    asm volatile("mma.sync.aligned.m16n8k16.row.col.f32.f16.f16.f32 "
                 "{%0,%1,%2,%3}, {%4,%5,%6,%7}, {%8,%9}, {%0,%1,%2,%3};"
                 : "+f"(c[0]), "+f"(c[1]), "+f"(c[2]), "+f"(c[3])
                 : "r"(a[0]), "r"(a[1]), "r"(a[2]), "r"(a[3]), "r"(b0), "r"(b1));
}

// ---------------- prep: int4 fake-quant weights (fp16) + BN fold ------------
__global__ void prep_kernel(const float* __restrict__ W,
                            const float* __restrict__ gamma,
                            const float* __restrict__ beta,
                            const float* __restrict__ mean,
                            const float* __restrict__ var) {
    int co = blockIdx.x;
    __shared__ float red[256];
    float m = 0.f;
    for (int i = threadIdx.x; i < CIN * 9; i += 256)
        m = fmaxf(m, fabsf(W[co * CIN * 9 + i]));
    red[threadIdx.x] = m;
    __syncthreads();
    for (int s = 128; s > 0; s >>= 1) {
        if (threadIdx.x < s)
            red[threadIdx.x] = fmaxf(red[threadIdx.x], red[threadIdx.x + s]);
        __syncthreads();
    }
    float scale = fmaxf(red[0] / 7.0f, 1e-8f);

    for (int i = threadIdx.x; i < CIN * 9; i += 256) {
        int ci = i / 9, r = i - ci * 9;
        float n = rintf(W[co * CIN * 9 + i] / scale);   // round-half-even
        n = fminf(fmaxf(n, -7.f), 7.f);                 // exact small int -> fp16 exact
        d_Wh[r * 4096 + co * 64 + ci] = __float2half_rn(n);
    }
    if (threadIdx.x == 0) {
        float istd = 1.0f / sqrtf(var[co] + 1e-5f);
        d_g[co]    = gamma[co] * istd * scale;          // weight scale folded in
        d_bias[co] = beta[co] - mean[co] * gamma[co] * istd;
    }
}

// ---------------- stage one input row (hi/lo fp16 split) --------------------
__device__ __forceinline__ void stage_row(const float* __restrict__ xb,
                                          char* basep, int R, int w0, int tid) {
    char* dst = basep + ((R + 1) % 3) * ROWBUF;
    bool rvalid = (unsigned)R < (unsigned)HH;
    for (int idx = tid; idx < 130 * 8; idx += 512) {
        int oct = idx / 130;            // ci octet 0..7
        int w   = idx - oct * 130;      // slot 0..129 (input w = w0-1+w)
        int gw  = w0 - 1 + w;
        uint32_t hi[4] = {0, 0, 0, 0}, lo[4] = {0, 0, 0, 0};
        if (rvalid && (unsigned)gw < (unsigned)WW) {
            const float* p = xb + (size_t)(oct * 8) * (HH * WW) + R * WW + gw;
            #pragma unroll
            for (int j = 0; j < 4; j++) {
                float f0 = p[(2 * j)     * (HH * WW)];
                float f1 = p[(2 * j + 1) * (HH * WW)];
                __half h0 = __float2half_rn(f0);
                __half h1 = __float2half_rn(f1);
                __half l0 = __float2half_rn(f0 - __half2float(h0));
                __half l1 = __float2half_rn(f1 - __half2float(h1));
                __half2 hp = __halves2half2(h0, h1);
                __half2 lp = __halves2half2(l0, l1);
                hi[j] = *(uint32_t*)&hp;
                lo[j] = *(uint32_t*)&lp;
            }
        }
        int off = w * XSLOT + oct * 16;
        *(uint4*)(dst + off)              = make_uint4(hi[0], hi[1], hi[2], hi[3]);
        *(uint4*)(dst + XROW_SPLIT + off) = make_uint4(lo[0], lo[1], lo[2], lo[3]);
    }
}

// ---------------- main fused conv+BN+QuantReLU (HMMA implicit GEMM) ---------
__global__ __launch_bounds__(512, 1)
void conv_kernel(const float* __restrict__ x,
                 const float* __restrict__ act_scale,
                 float* __restrict__ out) {
    extern __shared__ char basep[];
    const uint32_t base = smem_u32(basep);

    const int tid  = threadIdx.x;
    const int wid  = tid >> 5;
    const int lane = tid & 31;
    const int warp_m = wid & 3;        // cout 16-block
    const int warp_n = wid >> 2;       // pixel 32-block

    const int w0 = blockIdx.x * 128;
    const int h0 = blockIdx.y * TH;
    const int b  = blockIdx.z;
    const float* xb = x + (size_t)b * CIN * HH * WW;

    float* gs = (float*)(basep + MISC_OFF);
    float* bs = (float*)(basep + MISC_OFF + 256);

    // ---- prologue: BN params, weights, first two rows ----
    if (tid < COUT) { gs[tid] = d_g[tid]; bs[tid] = d_bias[tid]; }
    {
        const uint4* src = (const uint4*)d_Wh;
        for (int i = tid; i < 9 * 64 * 8; i += 512) {
            int tap = i >> 9, rem = i & 511;
            int co = rem >> 3, cq = rem & 7;
            *(uint4*)(basep + WB_OFF + tap * WTAP + co * XSLOT + cq * 16) = src[i];
        }
    }
    stage_row(xb, basep, h0 - 1, w0, tid);
    stage_row(xb, basep, h0,     w0, tid);

    // per-lane invariant ldmatrix address parts
    // A (weights, m16k16 row-major): lanes 0-7 m0-7/k0, 8-15 m8-15/k0,
    //                                16-23 m0-7/k8, 24-31 m8-15/k8
    const uint32_t arow = base + WB_OFF +
        (warp_m * 16 + (lane & 15)) * XSLOT + ((lane >> 4) & 1) * 16;
    // B (pixels, n8k16 col-major = [pixel][ci] row-major): lanes 0-7 p0-7/k0,
    //   8-15 p0-7/k8, 16-23 p8-15/k0, 24-31 p8-15/k8
    const uint32_t bpix = base +
        (warp_n * 32 + (lane & 7) + ((lane >> 4) << 3)) * XSLOT +
        ((lane >> 3) & 1) * 16;

    const float s = fmaxf(__ldg(act_scale), 1e-8f);
    // epilogue per-thread channels
    const int cA = warp_m * 16 + (lane >> 2);
    float g0, b0f, g1, b1f;

    for (int t = 0; t < TH; t++) {
        stage_row(xb, basep, h0 + t + 1, w0, tid);
        __syncthreads();
        if (t == 0) { g0 = gs[cA]; b0f = bs[cA]; g1 = gs[cA + 8]; b1f = bs[cA + 8]; }

        float acc[4][4];
        #pragma unroll
        for (int nt = 0; nt < 4; nt++)
            #pragma unroll
            for (int r = 0; r < 4; r++) acc[nt][r] = 0.f;

        #pragma unroll 1
        for (int kh = 0; kh < 3; kh++) {
            const uint32_t slotoff = ((h0 + t + kh) % 3) * ROWBUF;
            #pragma unroll
            for (int kw = 0; kw < 3; kw++) {
                const uint32_t atap = arow + (kh * 3 + kw) * WTAP;
                const uint32_t bkw  = bpix + slotoff + kw * XSLOT;
                #pragma unroll
                for (int kc = 0; kc < 4; kc++) {
                    uint32_t a[4];
                    ldsm_x4(a, atap + kc * 32);
                    #pragma unroll
                    for (int split = 0; split < 2; split++) {
                        uint32_t bb = bkw + split * XROW_SPLIT + kc * 32;
                        uint32_t bfr[8];
                        ldsm_x4(bfr,     bb);               // pixels n0-15
                        ldsm_x4(bfr + 4, bb + 16 * XSLOT);  // pixels n16-31
                        mma16816(acc[0], a, bfr[0], bfr[1]);
                        mma16816(acc[1], a, bfr[2], bfr[3]);
                        mma16816(acc[2], a, bfr[4], bfr[5]);
                        mma16816(acc[3], a, bfr[6], bfr[7]);
                    }
                }
            }
        }

        // ---- epilogue: BN + ReLU + uint4 fake-quant ----
        const int h = h0 + t;
        #pragma unroll
        for (int nt = 0; nt < 4; nt++) {
            const int p = w0 + warp_n * 32 + nt * 8 + 2 * (lane & 3);
            {   // rows cA (regs 0,1)
                float y0 = fmaxf(fmaf(acc[nt][0], g0, b0f), 0.f);
                float y1 = fmaxf(fmaf(acc[nt][1], g0, b0f), 0.f);
                float2 o;
                o.x = fminf(rintf(y0 / s), 15.f) * s;
                o.y = fminf(rintf(y1 / s), 15.f) * s;
                *(float2*)&out[(((size_t)b * COUT + cA) * HH + h) * WW + p] = o;
            }
            {   // rows cA+8 (regs 2,3)
                float y0 = fmaxf(fmaf(acc[nt][2], g1, b1f), 0.f);
                float y1 = fmaxf(fmaf(acc[nt][3], g1, b1f), 0.f);
                float2 o;
                o.x = fminf(rintf(y0 / s), 15.f) * s;
                o.y = fminf(rintf(y1 / s), 15.f) * s;
                *(float2*)&out[(((size_t)b * COUT + cA + 8) * HH + h) * WW + p] = o;
            }
        }
        __syncthreads();   // protect ring slot reuse by next stage_row
    }
}

// ---------------- harness entry ---------------------------------------------
extern "C" void kernel_launch(void* const* d_in, const int* in_sizes, int n_in,
                              void* d_out, int out_size) {
    const float* x     = (const float*)d_in[0];
    const float* W     = (const float*)d_in[1];
    const float* gamma = (const float*)d_in[2];
    const float* beta  = (const float*)d_in[3];
    const float* mean  = (const float*)d_in[4];
    const float* var   = (const float*)d_in[5];
    const float* act   = (const float*)d_in[6];
    float* out = (float*)d_out;
    (void)in_sizes; (void)n_in; (void)out_size;

    cudaFuncSetAttribute(conv_kernel, cudaFuncAttributeMaxDynamicSharedMemorySize,
                         SMEM_REQ);
    prep_kernel<<<COUT, 256>>>(W, gamma, beta, mean, var);
    dim3 grid(WW / 128, HH / TH, BATCH);
    conv_kernel<<<grid, 512, SMEM_REQ>>>(x, act, out);
}